// round 9
// baseline (speedup 1.0000x reference)
#include <cuda_runtime.h>
#include <cuda_fp16.h>

#define NUM_PL 50000
#define NUM_TR 100000
#define NUM_AR 10000
#define OFF_TR NUM_PL
#define OFF_AR (NUM_PL + NUM_TR)
#define NTOT   (NUM_PL + NUM_TR + NUM_AR)
#define HID    64
#define NADJ   4200000
#define SCAN_B 1024
#define NB     ((NTOT + SCAN_B - 1) / SCAN_B)   // 157

typedef unsigned long long ull;

// -------- scratch (device globals; no runtime allocation) --------
__device__ __align__(16) float  g_x  [(size_t)NTOT * HID];
__device__ __align__(16) float  g_y  [(size_t)NTOT * HID];
__device__ __align__(16) float  g_agg[(size_t)NTOT * HID];
__device__ __align__(16) __half g_h0 [(size_t)NTOT * HID];
__device__ __align__(16) __half g_h1 [(size_t)NTOT * HID];
__device__ int   g_deg [NTOT];
__device__ float g_rdeg[NTOT];
__device__ int   g_ptr [NTOT];
__device__ int   g_cur [NTOT];
__device__ __align__(16) int g_adj [NADJ];
__device__ int   g_bsum[NB];

// -------- helpers --------
__device__ __forceinline__ ull dup_f32(float x) {
    ull r; asm("mov.b64 %0, {%1,%1};" : "=l"(r) : "f"(x)); return r;
}
__device__ __forceinline__ void ffma2(ull& d, ull a, ull b) {
    asm("fma.rn.f32x2 %0, %1, %2, %3;" : "=l"(d) : "l"(a), "l"(b), "l"(d));
}
__device__ __forceinline__ float2 unpack2(ull v) {
    float2 f; asm("mov.b64 {%0,%1}, %2;" : "=f"(f.x), "=f"(f.y) : "l"(v)); return f;
}
__device__ __forceinline__ float2 h2f(unsigned u) {
    return __half22float2(*(const __half2*)&u);
}
__device__ __forceinline__ unsigned f2h2(float a, float b) {
    __half2 h = __floats2half2_rn(a, b);
    return *(const unsigned*)&h;
}

// -------- init playlist & artist rows --------
__global__ void init_emb_kernel(const float* __restrict__ pl_emb,
                                const float* __restrict__ ar_emb,
                                const float* __restrict__ type_emb) {
    int t = blockIdx.x * blockDim.x + threadIdx.x;
    int total = (NUM_PL + NUM_AR) * (HID / 4);
    if (t >= total) return;
    int node = t >> 4;
    int c    = (t & 15) * 4;
    const float* src; const float* ty; size_t row;
    if (node < NUM_PL) {
        src = pl_emb + (size_t)node * HID;
        row = (size_t)node * HID;
        ty  = type_emb;
    } else {
        int a = node - NUM_PL;
        src = ar_emb + (size_t)a * HID;
        row = (size_t)(OFF_AR + a) * HID;
        ty  = type_emb + 2 * HID;
    }
    float4 v  = *(const float4*)(src + c);
    float4 tv = *(const float4*)(ty  + c);
    v.x += tv.x; v.y += tv.y; v.z += tv.z; v.w += tv.w;
    *(float4*)(g_x + row + c) = v;
    uint2 h; h.x = f2h2(v.x, v.y); h.y = f2h2(v.z, v.w);
    *(uint2*)(g_h0 + row + c) = h;
}

__global__ void zero_deg_kernel() {
    int i = blockIdx.x * blockDim.x + threadIdx.x;
    if (i < NTOT) g_deg[i] = 0;
}

__global__ void deg_kernel(const int* __restrict__ s1, const int* __restrict__ d1, int n1,
                           const int* __restrict__ s2, const int* __restrict__ d2, int n2) {
    int e = blockIdx.x * blockDim.x + threadIdx.x;
    int a, b;
    if (e < n1)           { a = __ldg(s1 + e);               b = __ldg(d1 + e) + OFF_TR; }
    else if (e < n1 + n2) { a = __ldg(s2 + e - n1) + OFF_TR; b = __ldg(d2 + e - n1) + OFF_AR; }
    else return;
    atomicAdd(&g_deg[a], 1);
    atomicAdd(&g_deg[b], 1);
}

// -------- 2-pass scan (pass2 folded into pass3) --------
__device__ __forceinline__ int block_incl_scan(int v, int* warpsums) {
    int lane = threadIdx.x & 31, wid = threadIdx.x >> 5;
    int x = v;
#pragma unroll
    for (int o = 1; o < 32; o <<= 1) {
        int y = __shfl_up_sync(0xffffffffu, x, o);
        if (lane >= o) x += y;
    }
    if (lane == 31) warpsums[wid] = x;
    __syncthreads();
    if (threadIdx.x < 32) {
        int w = warpsums[threadIdx.x];
#pragma unroll
        for (int o = 1; o < 32; o <<= 1) {
            int y = __shfl_up_sync(0xffffffffu, w, o);
            if (threadIdx.x >= o) w += y;
        }
        warpsums[threadIdx.x] = w;
    }
    __syncthreads();
    if (wid > 0) x += warpsums[wid - 1];
    return x;
}

__global__ void scan_pass1() {
    __shared__ int warpsums[32];
    int i = blockIdx.x * SCAN_B + threadIdx.x;
    int v = (i < NTOT) ? g_deg[i] : 0;
    int x = block_incl_scan(v, warpsums);
    if (threadIdx.x == SCAN_B - 1) g_bsum[blockIdx.x] = x;
}

__global__ void scan_pass3() {
    __shared__ int warpsums[32];
    __shared__ int boff_s;
    {
        int bv = (threadIdx.x < NB) ? g_bsum[threadIdx.x] : 0;
        int bx = block_incl_scan(bv, warpsums);
        if (threadIdx.x == blockIdx.x) boff_s = bx - bv;
    }
    __syncthreads();
    int i = blockIdx.x * SCAN_B + threadIdx.x;
    int v = (i < NTOT) ? g_deg[i] : 0;
    int x = block_incl_scan(v, warpsums);
    if (i < NTOT) {
        int excl = x - v + boff_s;
        g_ptr[i] = excl;
        g_cur[i] = excl;
        g_rdeg[i] = 1.0f / (float)(v > 0 ? v : 1);
    }
}

__global__ void fill_kernel(const int* __restrict__ s1, const int* __restrict__ d1, int n1,
                            const int* __restrict__ s2, const int* __restrict__ d2, int n2) {
    int e = blockIdx.x * blockDim.x + threadIdx.x;
    int a, b;
    if (e < n1)           { a = __ldg(s1 + e);               b = __ldg(d1 + e) + OFF_TR; }
    else if (e < n1 + n2) { a = __ldg(s2 + e - n1) + OFF_TR; b = __ldg(d2 + e - n1) + OFF_AR; }
    else return;
    int pa = atomicAdd(&g_cur[a], 1);
    g_adj[pa] = b;
    int pb = atomicAdd(&g_cur[b], 1);
    g_adj[pb] = a;
}

// -------- gather aggregation v2: ONE WARP PER NODE --------
// lane = j*8 + cp : j = neighbor slot (0..3), cp = column part (8 halves = 16B).
// 8 neighbors consumed per iteration (2-deep unroll for MLP), zero divergence
// across nodes, shfl reduction over neighbor slots at the end.
__global__ void gather_kernel(int layer) {
    const __half* __restrict__ H = layer ? g_h1 : g_h0;
    int warpId = (blockIdx.x * blockDim.x + threadIdx.x) >> 5;
    if (warpId >= NTOT) return;
    const int lane = threadIdx.x & 31;
    const int j  = lane >> 3;        // neighbor slot
    const int cp = (lane & 7) * 8;   // half-column offset
    const int beg = g_ptr[warpId];
    const int d   = g_deg[warpId];

    float acc[8];
#pragma unroll
    for (int q = 0; q < 8; q++) acc[q] = 0.f;

    int i = 0;
    for (; i + 8 <= d; i += 8) {
        int s0 = __ldg(g_adj + beg + i + j);
        int s1 = __ldg(g_adj + beg + i + 4 + j);
        uint4 v0 = *(const uint4*)(H + (size_t)s0 * HID + cp);
        uint4 v1 = *(const uint4*)(H + (size_t)s1 * HID + cp);
#pragma unroll
        for (int q = 0; q < 4; q++) {
            float2 f0 = h2f((&v0.x)[q]);
            float2 f1 = h2f((&v1.x)[q]);
            acc[q * 2 + 0] += f0.x + f1.x;
            acc[q * 2 + 1] += f0.y + f1.y;
        }
    }
    for (; i < d; i += 4) {
        int idx = i + j;
        if (idx < d) {
            int s = __ldg(g_adj + beg + idx);
            uint4 v = *(const uint4*)(H + (size_t)s * HID + cp);
#pragma unroll
            for (int q = 0; q < 4; q++) {
                float2 f = h2f((&v.x)[q]);
                acc[q * 2 + 0] += f.x;
                acc[q * 2 + 1] += f.y;
            }
        }
    }

    // reduce over the 4 neighbor slots (lanes cp, cp+8, cp+16, cp+24)
#pragma unroll
    for (int q = 0; q < 8; q++) {
        acc[q] += __shfl_xor_sync(0xffffffffu, acc[q], 8);
        acc[q] += __shfl_xor_sync(0xffffffffu, acc[q], 16);
    }

    if (j == 0) {
        float rd = g_rdeg[warpId];
        float4 o0, o1;
        o0.x = acc[0] * rd; o0.y = acc[1] * rd; o0.z = acc[2] * rd; o0.w = acc[3] * rd;
        o1.x = acc[4] * rd; o1.y = acc[5] * rd; o1.z = acc[6] * rd; o1.w = acc[7] * rd;
        float* dst = g_agg + (size_t)warpId * HID + cp;
        *(float4*)dst       = o0;
        *(float4*)(dst + 4) = o1;
    }
}

// -------- fused GEMM with packed f32x2 FMAs (static smem) --------
__global__ void __launch_bounds__(128) gemm_kernel(
        const float* __restrict__ Aext, int aSel, int lda, int bSel,
        const float* __restrict__ W0, const float* __restrict__ W1,
        const float* __restrict__ bias, const float* __restrict__ bias2,
        float* __restrict__ outExt, int outSel, int outRowOff, int relu,
        int shadowSel) {
    __shared__ float Ws[64][68];
    __shared__ float rows[128][36];

    const float* __restrict__ A = (aSel == 2) ? g_agg : Aext;
    const float* __restrict__ B = (bSel == 0) ? g_x : (bSel == 1 ? g_y : nullptr);
    float* __restrict__ O = (outSel == 0) ? g_x : (outSel == 1 ? g_y : outExt);
    __half* __restrict__ S = (shadowSel == 0) ? g_h0 : (shadowSel == 1 ? g_h1 : nullptr);

    const int tid = threadIdx.x;
    const int tx  = tid & 15;
    const int ty  = tid >> 4;
    const int nodeBase = blockIdx.x * 32;

    for (int it = 0; it < 32; it++) {
        int node = nodeBase + it;
        int k = tid;
        float v;
        if (B) v = (k < HID) ? A[(size_t)node * lda + k]
                             : B[(size_t)node * HID + (k - HID)];
        else   v = A[(size_t)node * lda + k];
        rows[k][it] = v;
    }

    ull a01[4], a23[4];
#pragma unroll
    for (int i = 0; i < 4; i++) { a01[i] = 0ull; a23[i] = 0ull; }

    for (int h = 0; h < 2; h++) {
        __syncthreads();
        const float* Wsrc; int wstride, koff;
        if (W1) { Wsrc = h ? W1 : W0; wstride = 64;  koff = 0; }
        else    { Wsrc = W0;          wstride = 128; koff = h * 64; }
        for (int idx = tid; idx < 64 * 64; idx += 128) {
            int o = idx >> 6, k = idx & 63;
            Ws[k][o] = Wsrc[(size_t)o * wstride + koff + k];
        }
        __syncthreads();
#pragma unroll 8
        for (int k = 0; k < 64; k++) {
            ulonglong2 rp = *(const ulonglong2*)&rows[(h << 6) + k][ty * 4];
            float4 w = *(const float4*)&Ws[k][tx * 4];
            ull w0 = dup_f32(w.x), w1 = dup_f32(w.y);
            ull w2 = dup_f32(w.z), w3 = dup_f32(w.w);
            ffma2(a01[0], rp.x, w0); ffma2(a23[0], rp.y, w0);
            ffma2(a01[1], rp.x, w1); ffma2(a23[1], rp.y, w1);
            ffma2(a01[2], rp.x, w2); ffma2(a23[2], rp.y, w2);
            ffma2(a01[3], rp.x, w3); ffma2(a23[3], rp.y, w3);
        }
    }

    const int o = tx * 4;
    float b0 = bias[o], b1 = bias[o + 1], b2 = bias[o + 2], b3 = bias[o + 3];
    if (bias2) { b0 += bias2[o]; b1 += bias2[o + 1]; b2 += bias2[o + 2]; b3 += bias2[o + 3]; }

    float res[4][4];
#pragma unroll
    for (int i = 0; i < 4; i++) {
        float2 p = unpack2(a01[i]);
        float2 q = unpack2(a23[i]);
        res[0][i] = p.x; res[1][i] = p.y; res[2][i] = q.x; res[3][i] = q.y;
    }
#pragma unroll
    for (int j = 0; j < 4; j++) {
        size_t row = (size_t)(nodeBase + ty * 4 + j + outRowOff) * HID;
        float4 r;
        r.x = res[j][0] + b0; r.y = res[j][1] + b1;
        r.z = res[j][2] + b2; r.w = res[j][3] + b3;
        if (relu) {
            r.x = fmaxf(r.x, 0.f); r.y = fmaxf(r.y, 0.f);
            r.z = fmaxf(r.z, 0.f); r.w = fmaxf(r.w, 0.f);
        }
        *(float4*)(O + row + o) = r;
        if (S) {
            uint2 hh; hh.x = f2h2(r.x, r.y); hh.y = f2h2(r.z, r.w);
            *(uint2*)(S + row + o) = hh;
        }
    }
}

extern "C" void kernel_launch(void* const* d_in, const int* in_sizes, int n_in,
                              void* d_out, int out_size) {
    const float* track_x   = (const float*)d_in[0];
    const int*   pl_tr_src = (const int*)d_in[1];
    const int*   pl_tr_dst = (const int*)d_in[2];
    const int*   tr_ar_src = (const int*)d_in[3];
    const int*   tr_ar_dst = (const int*)d_in[4];
    const float* pl_emb    = (const float*)d_in[5];
    const float* ar_emb    = (const float*)d_in[6];
    const float* track_W   = (const float*)d_in[7];
    const float* track_b   = (const float*)d_in[8];
    const float* type_emb  = (const float*)d_in[9];
    const float* conv_Wl   = (const float*)d_in[10];
    const float* conv_bl   = (const float*)d_in[11];
    const float* conv_Wr   = (const float*)d_in[12];
    float* out = (float*)d_out;

    const int E1 = in_sizes[1];
    const int E2 = in_sizes[3];
    const int ET = E1 + E2;

    // lazily created side stream + events for capture-fork overlap
    static cudaStream_t s2 = nullptr;
    static cudaEvent_t evFork = nullptr, evJoin = nullptr;
    if (s2 == nullptr) {
        cudaStreamCreateWithFlags(&s2, cudaStreamNonBlocking);
        cudaEventCreateWithFlags(&evFork, cudaEventDisableTiming);
        cudaEventCreateWithFlags(&evJoin, cudaEventDisableTiming);
    }

    bool fork = (s2 != nullptr && evFork != nullptr && evJoin != nullptr);
    cudaStream_t sCsr = fork ? s2 : (cudaStream_t)0;
    if (fork) {
        cudaEventRecord(evFork, 0);
        cudaStreamWaitEvent(s2, evFork, 0);
    }

    // ---- branch A (default stream): node features (fp32 + fp16 shadow) ----
    {
        int total = (NUM_PL + NUM_AR) * (HID / 4);
        init_emb_kernel<<<(total + 255) / 256, 256>>>(pl_emb, ar_emb, type_emb);
    }
    gemm_kernel<<<NUM_TR / 32, 128>>>(track_x, -1, 128, /*bSel*/-1,
                                      track_W, nullptr,
                                      track_b, type_emb + HID,
                                      nullptr, /*outSel*/0, OFF_TR, /*relu*/0,
                                      /*shadowSel*/0);

    // ---- branch B (side stream): degrees + CSR ----
    zero_deg_kernel<<<(NTOT + 255) / 256, 256, 0, sCsr>>>();
    deg_kernel<<<(ET + 255) / 256, 256, 0, sCsr>>>(pl_tr_src, pl_tr_dst, E1,
                                                   tr_ar_src, tr_ar_dst, E2);
    scan_pass1<<<NB, SCAN_B, 0, sCsr>>>();
    scan_pass3<<<NB, SCAN_B, 0, sCsr>>>();
    fill_kernel<<<(ET + 255) / 256, 256, 0, sCsr>>>(pl_tr_src, pl_tr_dst, E1,
                                                    tr_ar_src, tr_ar_dst, E2);
    if (fork) {
        cudaEventRecord(evJoin, s2);
        cudaStreamWaitEvent((cudaStream_t)0, evJoin, 0);
    }

    // ---- layer 0: g_h0/g_x -> g_y (+g_h1) ----
    gather_kernel<<<(NTOT * 32 + 255) / 256, 256>>>(0);
    gemm_kernel<<<NTOT / 32, 128>>>(nullptr, 2, HID, /*bSel*/0,
                                    conv_Wl, conv_Wr, conv_bl, nullptr,
                                    nullptr, /*outSel*/1, 0, /*relu*/1,
                                    /*shadowSel*/1);

    // ---- layer 1: g_h1/g_y -> d_out ----
    gather_kernel<<<(NTOT * 32 + 255) / 256, 256>>>(1);
    gemm_kernel<<<NTOT / 32, 128>>>(nullptr, 2, HID, /*bSel*/1,
                                    conv_Wl + 64 * 64, conv_Wr + 64 * 64,
                                    conv_bl + 64, nullptr,
                                    out, /*outSel*/-1, 0, /*relu*/1,
                                    /*shadowSel*/-1);
}

// round 10
// speedup vs baseline: 1.6426x; 1.6426x over previous
#include <cuda_runtime.h>
#include <cuda_fp16.h>

#define NUM_PL 50000
#define NUM_TR 100000
#define NUM_AR 10000
#define OFF_TR NUM_PL
#define OFF_AR (NUM_PL + NUM_TR)
#define NTOT   (NUM_PL + NUM_TR + NUM_AR)
#define HID    64
#define NADJ   4200000
#define SCAN_B 1024
#define NB     ((NTOT + SCAN_B - 1) / SCAN_B)   // 157

typedef unsigned long long ull;

// -------- scratch (device globals; no runtime allocation) --------
__device__ __align__(16) float  g_x   [(size_t)NTOT * HID];
__device__ __align__(16) __half g_h0  [(size_t)NTOT * HID];  // fp16 features, layer-0 input
__device__ __align__(16) __half g_h1  [(size_t)NTOT * HID];  // fp16 features, layer-1 input
__device__ __align__(16) __half g_aggh[(size_t)NTOT * HID];  // fp16 aggregated neighbors
__device__ __align__(16) __half g_wh  [2 * 64 * 128];        // fp16 [Wl|Wr] per layer
__device__ int   g_deg [NTOT];
__device__ float g_rdeg[NTOT];
__device__ int   g_ptr [NTOT];
__device__ int   g_cur [NTOT];
__device__ __align__(16) int g_adj [NADJ];
__device__ int   g_bsum[NB];

// -------- helpers --------
__device__ __forceinline__ ull dup_f32(float x) {
    ull r; asm("mov.b64 %0, {%1,%1};" : "=l"(r) : "f"(x)); return r;
}
__device__ __forceinline__ void ffma2(ull& d, ull a, ull b) {
    asm("fma.rn.f32x2 %0, %1, %2, %3;" : "=l"(d) : "l"(a), "l"(b), "l"(d));
}
__device__ __forceinline__ float2 unpack2(ull v) {
    float2 f; asm("mov.b64 {%0,%1}, %2;" : "=f"(f.x), "=f"(f.y) : "l"(v)); return f;
}
__device__ __forceinline__ float2 h2f(unsigned u) {
    return __half22float2(*(const __half2*)&u);
}
__device__ __forceinline__ __half2 u2h(unsigned u) {
    return *(const __half2*)&u;
}
__device__ __forceinline__ unsigned f2h2(float a, float b) {
    __half2 h = __floats2half2_rn(a, b);
    return *(const unsigned*)&h;
}
__device__ __forceinline__ void mma_f16(float* c, unsigned a0, unsigned a1,
                                        unsigned a2, unsigned a3,
                                        unsigned b0, unsigned b1) {
    asm volatile("mma.sync.aligned.m16n8k16.row.col.f32.f16.f16.f32 "
                 "{%0,%1,%2,%3}, {%4,%5,%6,%7}, {%8,%9}, {%0,%1,%2,%3};"
                 : "+f"(c[0]), "+f"(c[1]), "+f"(c[2]), "+f"(c[3])
                 : "r"(a0), "r"(a1), "r"(a2), "r"(a3), "r"(b0), "r"(b1));
}

// -------- init playlist & artist rows --------
__global__ void init_emb_kernel(const float* __restrict__ pl_emb,
                                const float* __restrict__ ar_emb,
                                const float* __restrict__ type_emb) {
    int t = blockIdx.x * blockDim.x + threadIdx.x;
    int total = (NUM_PL + NUM_AR) * (HID / 4);
    if (t >= total) return;
    int node = t >> 4;
    int c    = (t & 15) * 4;
    const float* src; const float* ty; size_t row;
    if (node < NUM_PL) {
        src = pl_emb + (size_t)node * HID;
        row = (size_t)node * HID;
        ty  = type_emb;
    } else {
        int a = node - NUM_PL;
        src = ar_emb + (size_t)a * HID;
        row = (size_t)(OFF_AR + a) * HID;
        ty  = type_emb + 2 * HID;
    }
    float4 v  = *(const float4*)(src + c);
    float4 tv = *(const float4*)(ty  + c);
    v.x += tv.x; v.y += tv.y; v.z += tv.z; v.w += tv.w;
    uint2 h; h.x = f2h2(v.x, v.y); h.y = f2h2(v.z, v.w);
    *(uint2*)(g_h0 + row + c) = h;
}

// -------- weight pre-convert: g_wh[l][o*128 + k] = fp16([Wl|Wr]) --------
__global__ void wconv_kernel(const float* __restrict__ Wl,
                             const float* __restrict__ Wr) {
    int t = blockIdx.x * blockDim.x + threadIdx.x;
    if (t >= 2 * 64 * 128) return;
    int l = t >> 13;
    int o = (t >> 7) & 63;
    int k = t & 127;
    float v = (k < 64) ? Wl[l * 64 * 64 + o * 64 + k]
                       : Wr[l * 64 * 64 + o * 64 + (k - 64)];
    g_wh[t] = __float2half_rn(v);
}

__global__ void zero_deg_kernel() {
    int i = blockIdx.x * blockDim.x + threadIdx.x;
    if (i < NTOT) g_deg[i] = 0;
}

__global__ void deg_kernel(const int* __restrict__ s1, const int* __restrict__ d1, int n1,
                           const int* __restrict__ s2, const int* __restrict__ d2, int n2) {
    int e = blockIdx.x * blockDim.x + threadIdx.x;
    int a, b;
    if (e < n1)           { a = __ldg(s1 + e);               b = __ldg(d1 + e) + OFF_TR; }
    else if (e < n1 + n2) { a = __ldg(s2 + e - n1) + OFF_TR; b = __ldg(d2 + e - n1) + OFF_AR; }
    else return;
    atomicAdd(&g_deg[a], 1);
    atomicAdd(&g_deg[b], 1);
}

// -------- 2-pass scan (pass2 folded into pass3) --------
__device__ __forceinline__ int block_incl_scan(int v, int* warpsums) {
    int lane = threadIdx.x & 31, wid = threadIdx.x >> 5;
    int x = v;
#pragma unroll
    for (int o = 1; o < 32; o <<= 1) {
        int y = __shfl_up_sync(0xffffffffu, x, o);
        if (lane >= o) x += y;
    }
    if (lane == 31) warpsums[wid] = x;
    __syncthreads();
    if (threadIdx.x < 32) {
        int w = warpsums[threadIdx.x];
#pragma unroll
        for (int o = 1; o < 32; o <<= 1) {
            int y = __shfl_up_sync(0xffffffffu, w, o);
            if (threadIdx.x >= o) w += y;
        }
        warpsums[threadIdx.x] = w;
    }
    __syncthreads();
    if (wid > 0) x += warpsums[wid - 1];
    return x;
}

__global__ void scan_pass1() {
    __shared__ int warpsums[32];
    int i = blockIdx.x * SCAN_B + threadIdx.x;
    int v = (i < NTOT) ? g_deg[i] : 0;
    int x = block_incl_scan(v, warpsums);
    if (threadIdx.x == SCAN_B - 1) g_bsum[blockIdx.x] = x;
}

__global__ void scan_pass3() {
    __shared__ int warpsums[32];
    __shared__ int boff_s;
    {
        int bv = (threadIdx.x < NB) ? g_bsum[threadIdx.x] : 0;
        int bx = block_incl_scan(bv, warpsums);
        if (threadIdx.x == blockIdx.x) boff_s = bx - bv;
    }
    __syncthreads();
    int i = blockIdx.x * SCAN_B + threadIdx.x;
    int v = (i < NTOT) ? g_deg[i] : 0;
    int x = block_incl_scan(v, warpsums);
    if (i < NTOT) {
        int excl = x - v + boff_s;
        g_ptr[i] = excl;
        g_cur[i] = excl;
        g_rdeg[i] = 1.0f / (float)(v > 0 ? v : 1);
    }
}

__global__ void fill_kernel(const int* __restrict__ s1, const int* __restrict__ d1, int n1,
                            const int* __restrict__ s2, const int* __restrict__ d2, int n2) {
    int e = blockIdx.x * blockDim.x + threadIdx.x;
    int a, b;
    if (e < n1)           { a = __ldg(s1 + e);               b = __ldg(d1 + e) + OFF_TR; }
    else if (e < n1 + n2) { a = __ldg(s2 + e - n1) + OFF_TR; b = __ldg(d2 + e - n1) + OFF_AR; }
    else return;
    int pa = atomicAdd(&g_cur[a], 1);
    g_adj[pa] = b;
    int pb = atomicAdd(&g_cur[b], 1);
    g_adj[pb] = a;
}

// -------- gather aggregation (r8 layout): 8 lanes/node, HADD2 tree per 4 --------
// writes fp16 g_aggh (mean over neighbors).
__global__ void gather_kernel(int layer) {
    const __half* __restrict__ H = layer ? g_h1 : g_h0;
    int t = blockIdx.x * blockDim.x + threadIdx.x;
    int node = t >> 3;
    if (node >= NTOT) return;
    int c = (t & 7) * 8;
    int beg = g_ptr[node];
    int d   = g_deg[node];
    float acc[8];
#pragma unroll
    for (int j = 0; j < 8; j++) acc[j] = 0.f;

    int i = 0;
    int mis = beg & 3;
    int peel = mis ? (4 - mis) : 0;
    if (peel > d) peel = d;
    for (; i < peel; i++) {
        int s = __ldg(g_adj + beg + i);
        uint4 v = *(const uint4*)(H + (size_t)s * HID + c);
#pragma unroll
        for (int q = 0; q < 4; q++) {
            float2 f = h2f((&v.x)[q]);
            acc[q * 2 + 0] += f.x; acc[q * 2 + 1] += f.y;
        }
    }
    for (; i + 4 <= d; i += 4) {
        int4 s = *(const int4*)(g_adj + beg + i);
        uint4 v0 = *(const uint4*)(H + (size_t)s.x * HID + c);
        uint4 v1 = *(const uint4*)(H + (size_t)s.y * HID + c);
        uint4 v2 = *(const uint4*)(H + (size_t)s.z * HID + c);
        uint4 v3 = *(const uint4*)(H + (size_t)s.w * HID + c);
#pragma unroll
        for (int q = 0; q < 4; q++) {
            __half2 sh = __hadd2(__hadd2(u2h((&v0.x)[q]), u2h((&v1.x)[q])),
                                 __hadd2(u2h((&v2.x)[q]), u2h((&v3.x)[q])));
            float2 f = __half22float2(sh);
            acc[q * 2 + 0] += f.x; acc[q * 2 + 1] += f.y;
        }
    }
    for (; i < d; i++) {
        int s = __ldg(g_adj + beg + i);
        uint4 v = *(const uint4*)(H + (size_t)s * HID + c);
#pragma unroll
        for (int q = 0; q < 4; q++) {
            float2 f = h2f((&v.x)[q]);
            acc[q * 2 + 0] += f.x; acc[q * 2 + 1] += f.y;
        }
    }

    float rd = g_rdeg[node];
    uint4 hv;
    hv.x = f2h2(acc[0] * rd, acc[1] * rd);
    hv.y = f2h2(acc[2] * rd, acc[3] * rd);
    hv.z = f2h2(acc[4] * rd, acc[5] * rd);
    hv.w = f2h2(acc[6] * rd, acc[7] * rd);
    *(uint4*)(g_aggh + (size_t)node * HID + c) = hv;
}

// -------- track GEMM (exact f32x2): g_x/g_h0[tr] = track_x @ W^T + b + type_emb[1] --------
__global__ void __launch_bounds__(128) track_gemm_kernel(
        const float* __restrict__ A, const float* __restrict__ W,
        const float* __restrict__ bias, const float* __restrict__ bias2) {
    __shared__ float Ws[64][68];
    __shared__ float rows[128][36];
    const int tid = threadIdx.x;
    const int tx  = tid & 15;
    const int ty  = tid >> 4;
    const int nodeBase = blockIdx.x * 32;

    for (int it = 0; it < 32; it++)
        rows[tid][it] = A[(size_t)(nodeBase + it) * 128 + tid];

    ull a01[4], a23[4];
#pragma unroll
    for (int i = 0; i < 4; i++) { a01[i] = 0ull; a23[i] = 0ull; }

    for (int h = 0; h < 2; h++) {
        __syncthreads();
        for (int idx = tid; idx < 64 * 64; idx += 128) {
            int o = idx >> 6, k = idx & 63;
            Ws[k][o] = W[(size_t)o * 128 + h * 64 + k];
        }
        __syncthreads();
#pragma unroll 8
        for (int k = 0; k < 64; k++) {
            ulonglong2 rp = *(const ulonglong2*)&rows[(h << 6) + k][ty * 4];
            float4 w = *(const float4*)&Ws[k][tx * 4];
            ull w0 = dup_f32(w.x), w1 = dup_f32(w.y);
            ull w2 = dup_f32(w.z), w3 = dup_f32(w.w);
            ffma2(a01[0], rp.x, w0); ffma2(a23[0], rp.y, w0);
            ffma2(a01[1], rp.x, w1); ffma2(a23[1], rp.y, w1);
            ffma2(a01[2], rp.x, w2); ffma2(a23[2], rp.y, w2);
            ffma2(a01[3], rp.x, w3); ffma2(a23[3], rp.y, w3);
        }
    }

    const int o = tx * 4;
    float b0 = bias[o] + bias2[o],         b1 = bias[o + 1] + bias2[o + 1];
    float b2 = bias[o + 2] + bias2[o + 2], b3 = bias[o + 3] + bias2[o + 3];
    float res[4][4];
#pragma unroll
    for (int i = 0; i < 4; i++) {
        float2 p = unpack2(a01[i]);
        float2 q = unpack2(a23[i]);
        res[0][i] = p.x; res[1][i] = p.y; res[2][i] = q.x; res[3][i] = q.y;
    }
#pragma unroll
    for (int j = 0; j < 4; j++) {
        size_t row = (size_t)(nodeBase + ty * 4 + j + OFF_TR) * HID;
        float4 r;
        r.x = res[j][0] + b0; r.y = res[j][1] + b1;
        r.z = res[j][2] + b2; r.w = res[j][3] + b3;
        uint2 hh; hh.x = f2h2(r.x, r.y); hh.y = f2h2(r.z, r.w);
        *(uint2*)(g_h0 + row + o) = hh;
    }
}

// -------- conv layer via fp16 mma.sync (m16n8k16, fp32 accum) --------
// 64 nodes/block, 128 threads; warp w handles nodes w*16..+15, all 64 outputs.
// A = [g_aggh | g_h(layer)] fp16, W = g_wh[layer] fp16. Padded stride 136
// halves -> all fragment LDS are bank-conflict-free.
__global__ void __launch_bounds__(128) conv_mma_kernel(
        int layer, const float* __restrict__ bias, float* __restrict__ outExt) {
    __shared__ __half A_s[64][136];
    __shared__ __half W_s[64][136];
    const __half* __restrict__ Hroot = layer ? g_h1 : g_h0;
    const __half* __restrict__ Wh = g_wh + layer * 64 * 128;

    const int tid  = threadIdx.x;
    const int lane = tid & 31;
    const int warp = tid >> 5;
    const int nodeBase = blockIdx.x * 64;

    for (int idx = tid; idx < 1024; idx += 128) {
        int n = idx >> 4, k8 = idx & 15;
        uint4 v;
        if (k8 < 8) v = *(const uint4*)(g_aggh + (size_t)(nodeBase + n) * HID + k8 * 8);
        else        v = *(const uint4*)(Hroot  + (size_t)(nodeBase + n) * HID + (k8 - 8) * 8);
        *(uint4*)&A_s[n][k8 * 8] = v;
    }
    for (int idx = tid; idx < 1024; idx += 128) {
        int o = idx >> 4, k8 = idx & 15;
        *(uint4*)&W_s[o][k8 * 8] = *(const uint4*)(Wh + o * 128 + k8 * 8);
    }
    __syncthreads();

    float c[8][4];
#pragma unroll
    for (int t8 = 0; t8 < 8; t8++)
#pragma unroll
        for (int i = 0; i < 4; i++) c[t8][i] = 0.f;

    const int row = warp * 16 + (lane >> 2);   // lower row of the pair
    const int kq  = (lane & 3) * 2;
    const int nb  = lane >> 2;

#pragma unroll
    for (int s = 0; s < 8; s++) {
        int k0 = s * 16;
        unsigned a0 = *(const unsigned*)&A_s[row][k0 + kq];
        unsigned a1 = *(const unsigned*)&A_s[row + 8][k0 + kq];
        unsigned a2 = *(const unsigned*)&A_s[row][k0 + 8 + kq];
        unsigned a3 = *(const unsigned*)&A_s[row + 8][k0 + 8 + kq];
#pragma unroll
        for (int t8 = 0; t8 < 8; t8++) {
            unsigned b0 = *(const unsigned*)&W_s[t8 * 8 + nb][k0 + kq];
            unsigned b1 = *(const unsigned*)&W_s[t8 * 8 + nb][k0 + 8 + kq];
            mma_f16(c[t8], a0, a1, a2, a3, b0, b1);
        }
    }

    const int col0 = (lane & 3) * 2;
#pragma unroll
    for (int t8 = 0; t8 < 8; t8++) {
        int col = t8 * 8 + col0;
        float bc0 = bias[col], bc1 = bias[col + 1];
        float r0 = fmaxf(c[t8][0] + bc0, 0.f);
        float r1 = fmaxf(c[t8][1] + bc1, 0.f);
        float r2 = fmaxf(c[t8][2] + bc0, 0.f);
        float r3 = fmaxf(c[t8][3] + bc1, 0.f);
        size_t rA = (size_t)(nodeBase + row) * HID + col;
        size_t rB = (size_t)(nodeBase + row + 8) * HID + col;
        if (layer == 0) {
            *(unsigned*)(g_h1 + rA) = f2h2(r0, r1);
            *(unsigned*)(g_h1 + rB) = f2h2(r2, r3);
        } else {
            *(float2*)(outExt + rA) = make_float2(r0, r1);
            *(float2*)(outExt + rB) = make_float2(r2, r3);
        }
    }
}

extern "C" void kernel_launch(void* const* d_in, const int* in_sizes, int n_in,
                              void* d_out, int out_size) {
    const float* track_x   = (const float*)d_in[0];
    const int*   pl_tr_src = (const int*)d_in[1];
    const int*   pl_tr_dst = (const int*)d_in[2];
    const int*   tr_ar_src = (const int*)d_in[3];
    const int*   tr_ar_dst = (const int*)d_in[4];
    const float* pl_emb    = (const float*)d_in[5];
    const float* ar_emb    = (const float*)d_in[6];
    const float* track_W   = (const float*)d_in[7];
    const float* track_b   = (const float*)d_in[8];
    const float* type_emb  = (const float*)d_in[9];
    const float* conv_Wl   = (const float*)d_in[10];
    const float* conv_bl   = (const float*)d_in[11];
    const float* conv_Wr   = (const float*)d_in[12];
    float* out = (float*)d_out;

    const int E1 = in_sizes[1];
    const int E2 = in_sizes[3];
    const int ET = E1 + E2;

    // lazily created side stream + events for capture-fork overlap
    static cudaStream_t s2 = nullptr;
    static cudaEvent_t evFork = nullptr, evJoin = nullptr;
    if (s2 == nullptr) {
        cudaStreamCreateWithFlags(&s2, cudaStreamNonBlocking);
        cudaEventCreateWithFlags(&evFork, cudaEventDisableTiming);
        cudaEventCreateWithFlags(&evJoin, cudaEventDisableTiming);
    }
    bool fork = (s2 != nullptr && evFork != nullptr && evJoin != nullptr);
    cudaStream_t sCsr = fork ? s2 : (cudaStream_t)0;
    if (fork) {
        cudaEventRecord(evFork, 0);
        cudaStreamWaitEvent(s2, evFork, 0);
    }

    // ---- branch A (default stream): node features (fp16) ----
    {
        int total = (NUM_PL + NUM_AR) * (HID / 4);
        init_emb_kernel<<<(total + 255) / 256, 256>>>(pl_emb, ar_emb, type_emb);
    }
    track_gemm_kernel<<<NUM_TR / 32, 128>>>(track_x, track_W, track_b,
                                            type_emb + HID);

    // ---- branch B (side stream): weights + degrees + CSR ----
    wconv_kernel<<<(2 * 64 * 128 + 255) / 256, 256, 0, sCsr>>>(conv_Wl, conv_Wr);
    zero_deg_kernel<<<(NTOT + 255) / 256, 256, 0, sCsr>>>();
    deg_kernel<<<(ET + 255) / 256, 256, 0, sCsr>>>(pl_tr_src, pl_tr_dst, E1,
                                                   tr_ar_src, tr_ar_dst, E2);
    scan_pass1<<<NB, SCAN_B, 0, sCsr>>>();
    scan_pass3<<<NB, SCAN_B, 0, sCsr>>>();
    fill_kernel<<<(ET + 255) / 256, 256, 0, sCsr>>>(pl_tr_src, pl_tr_dst, E1,
                                                    tr_ar_src, tr_ar_dst, E2);
    if (fork) {
        cudaEventRecord(evJoin, s2);
        cudaStreamWaitEvent((cudaStream_t)0, evJoin, 0);
    }

    // ---- layer 0: g_h0 -> g_h1 ----
    gather_kernel<<<(NTOT * 8 + 255) / 256, 256>>>(0);
    conv_mma_kernel<<<NTOT / 64, 128>>>(0, conv_bl, nullptr);

    // ---- layer 1: g_h1 -> d_out ----
    gather_kernel<<<(NTOT * 8 + 255) / 256, 256>>>(1);
    conv_mma_kernel<<<NTOT / 64, 128>>>(1, conv_bl + 64, out);
}

// round 11
// speedup vs baseline: 1.6563x; 1.0083x over previous
#include <cuda_runtime.h>
#include <cuda_fp16.h>

#define NUM_PL 50000
#define NUM_TR 100000
#define NUM_AR 10000
#define OFF_TR NUM_PL
#define OFF_AR (NUM_PL + NUM_TR)
#define NTOT   (NUM_PL + NUM_TR + NUM_AR)
#define HID    64
#define MAXDEG 128            // fixed adjacency stride; true max deg ~70

typedef unsigned long long ull;

// -------- scratch (device globals; no runtime allocation) --------
__device__ __align__(16) __half g_h0  [(size_t)NTOT * HID];  // fp16 features, layer-0 input
__device__ __align__(16) __half g_h1  [(size_t)NTOT * HID];  // fp16 features, layer-1 input
__device__ __align__(16) __half g_aggh[(size_t)NTOT * HID];  // fp16 aggregated neighbors
__device__ __align__(16) __half g_wh  [2 * 64 * 128];        // fp16 [Wl|Wr] per layer
__device__ int g_deg[NTOT];
__device__ __align__(16) int g_adj[(size_t)NTOT * MAXDEG];   // fixed-stride adjacency

// -------- helpers --------
__device__ __forceinline__ ull dup_f32(float x) {
    ull r; asm("mov.b64 %0, {%1,%1};" : "=l"(r) : "f"(x)); return r;
}
__device__ __forceinline__ void ffma2(ull& d, ull a, ull b) {
    asm("fma.rn.f32x2 %0, %1, %2, %3;" : "=l"(d) : "l"(a), "l"(b), "l"(d));
}
__device__ __forceinline__ float2 unpack2(ull v) {
    float2 f; asm("mov.b64 {%0,%1}, %2;" : "=f"(f.x), "=f"(f.y) : "l"(v)); return f;
}
__device__ __forceinline__ float2 h2f(unsigned u) {
    return __half22float2(*(const __half2*)&u);
}
__device__ __forceinline__ __half2 u2h(unsigned u) {
    return *(const __half2*)&u;
}
__device__ __forceinline__ unsigned f2h2(float a, float b) {
    __half2 h = __floats2half2_rn(a, b);
    return *(const unsigned*)&h;
}
__device__ __forceinline__ void mma_f16(float* c, unsigned a0, unsigned a1,
                                        unsigned a2, unsigned a3,
                                        unsigned b0, unsigned b1) {
    asm volatile("mma.sync.aligned.m16n8k16.row.col.f32.f16.f16.f32 "
                 "{%0,%1,%2,%3}, {%4,%5,%6,%7}, {%8,%9}, {%0,%1,%2,%3};"
                 : "+f"(c[0]), "+f"(c[1]), "+f"(c[2]), "+f"(c[3])
                 : "r"(a0), "r"(a1), "r"(a2), "r"(a3), "r"(b0), "r"(b1));
}

// -------- init playlist & artist rows (fp16) --------
__global__ void init_emb_kernel(const float* __restrict__ pl_emb,
                                const float* __restrict__ ar_emb,
                                const float* __restrict__ type_emb) {
    int t = blockIdx.x * blockDim.x + threadIdx.x;
    int total = (NUM_PL + NUM_AR) * (HID / 4);
    if (t >= total) return;
    int node = t >> 4;
    int c    = (t & 15) * 4;
    const float* src; const float* ty; size_t row;
    if (node < NUM_PL) {
        src = pl_emb + (size_t)node * HID;
        row = (size_t)node * HID;
        ty  = type_emb;
    } else {
        int a = node - NUM_PL;
        src = ar_emb + (size_t)a * HID;
        row = (size_t)(OFF_AR + a) * HID;
        ty  = type_emb + 2 * HID;
    }
    float4 v  = *(const float4*)(src + c);
    float4 tv = *(const float4*)(ty  + c);
    v.x += tv.x; v.y += tv.y; v.z += tv.z; v.w += tv.w;
    uint2 h; h.x = f2h2(v.x, v.y); h.y = f2h2(v.z, v.w);
    *(uint2*)(g_h0 + row + c) = h;
}

// -------- weight pre-convert: g_wh[l][o*128 + k] = fp16([Wl|Wr]) --------
__global__ void wconv_kernel(const float* __restrict__ Wl,
                             const float* __restrict__ Wr) {
    int t = blockIdx.x * blockDim.x + threadIdx.x;
    if (t >= 2 * 64 * 128) return;
    int l = t >> 13;
    int o = (t >> 7) & 63;
    int k = t & 127;
    float v = (k < 64) ? Wl[l * 64 * 64 + o * 64 + k]
                       : Wr[l * 64 * 64 + o * 64 + (k - 64)];
    g_wh[t] = __float2half_rn(v);
}

__global__ void zero_deg_kernel() {
    int i = blockIdx.x * blockDim.x + threadIdx.x;
    if (i < NTOT) g_deg[i] = 0;
}

// -------- single-pass CSR build: count + place in one kernel --------
__global__ void fill_kernel(const int* __restrict__ s1, const int* __restrict__ d1, int n1,
                            const int* __restrict__ s2, const int* __restrict__ d2, int n2) {
    int e = blockIdx.x * blockDim.x + threadIdx.x;
    int a, b;
    if (e < n1)           { a = __ldg(s1 + e);               b = __ldg(d1 + e) + OFF_TR; }
    else if (e < n1 + n2) { a = __ldg(s2 + e - n1) + OFF_TR; b = __ldg(d2 + e - n1) + OFF_AR; }
    else return;
    int pa = atomicAdd(&g_deg[a], 1);
    if (pa < MAXDEG) g_adj[(size_t)a * MAXDEG + pa] = b;
    int pb = atomicAdd(&g_deg[b], 1);
    if (pb < MAXDEG) g_adj[(size_t)b * MAXDEG + pb] = a;
}

// -------- gather aggregation: 8 lanes/node, HADD2 tree per 4 neighbors --------
// fixed-stride adjacency: beg always 16B-aligned, no peel. rdeg inline.
__global__ void gather_kernel(int layer) {
    const __half* __restrict__ H = layer ? g_h1 : g_h0;
    int t = blockIdx.x * blockDim.x + threadIdx.x;
    int node = t >> 3;
    if (node >= NTOT) return;
    int c = (t & 7) * 8;
    const int* __restrict__ adj = g_adj + (size_t)node * MAXDEG;
    int d = g_deg[node];
    if (d > MAXDEG) d = MAXDEG;
    float acc[8];
#pragma unroll
    for (int j = 0; j < 8; j++) acc[j] = 0.f;

    int i = 0;
    for (; i + 4 <= d; i += 4) {
        int4 s = *(const int4*)(adj + i);
        uint4 v0 = *(const uint4*)(H + (size_t)s.x * HID + c);
        uint4 v1 = *(const uint4*)(H + (size_t)s.y * HID + c);
        uint4 v2 = *(const uint4*)(H + (size_t)s.z * HID + c);
        uint4 v3 = *(const uint4*)(H + (size_t)s.w * HID + c);
#pragma unroll
        for (int q = 0; q < 4; q++) {
            __half2 sh = __hadd2(__hadd2(u2h((&v0.x)[q]), u2h((&v1.x)[q])),
                                 __hadd2(u2h((&v2.x)[q]), u2h((&v3.x)[q])));
            float2 f = __half22float2(sh);
            acc[q * 2 + 0] += f.x; acc[q * 2 + 1] += f.y;
        }
    }
    for (; i < d; i++) {
        int s = __ldg(adj + i);
        uint4 v = *(const uint4*)(H + (size_t)s * HID + c);
#pragma unroll
        for (int q = 0; q < 4; q++) {
            float2 f = h2f((&v.x)[q]);
            acc[q * 2 + 0] += f.x; acc[q * 2 + 1] += f.y;
        }
    }

    float rd = 1.0f / (float)(d > 0 ? d : 1);
    uint4 hv;
    hv.x = f2h2(acc[0] * rd, acc[1] * rd);
    hv.y = f2h2(acc[2] * rd, acc[3] * rd);
    hv.z = f2h2(acc[4] * rd, acc[5] * rd);
    hv.w = f2h2(acc[6] * rd, acc[7] * rd);
    *(uint4*)(g_aggh + (size_t)node * HID + c) = hv;
}

// -------- track GEMM (exact f32x2): g_h0[tr] = fp16(track_x @ W^T + b + type_emb[1]) --------
__global__ void __launch_bounds__(128) track_gemm_kernel(
        const float* __restrict__ A, const float* __restrict__ W,
        const float* __restrict__ bias, const float* __restrict__ bias2) {
    __shared__ float Ws[64][68];
    __shared__ float rows[128][36];
    const int tid = threadIdx.x;
    const int tx  = tid & 15;
    const int ty  = tid >> 4;
    const int nodeBase = blockIdx.x * 32;

    for (int it = 0; it < 32; it++)
        rows[tid][it] = A[(size_t)(nodeBase + it) * 128 + tid];

    ull a01[4], a23[4];
#pragma unroll
    for (int i = 0; i < 4; i++) { a01[i] = 0ull; a23[i] = 0ull; }

    for (int h = 0; h < 2; h++) {
        __syncthreads();
        for (int idx = tid; idx < 64 * 64; idx += 128) {
            int o = idx >> 6, k = idx & 63;
            Ws[k][o] = W[(size_t)o * 128 + h * 64 + k];
        }
        __syncthreads();
#pragma unroll 8
        for (int k = 0; k < 64; k++) {
            ulonglong2 rp = *(const ulonglong2*)&rows[(h << 6) + k][ty * 4];
            float4 w = *(const float4*)&Ws[k][tx * 4];
            ull w0 = dup_f32(w.x), w1 = dup_f32(w.y);
            ull w2 = dup_f32(w.z), w3 = dup_f32(w.w);
            ffma2(a01[0], rp.x, w0); ffma2(a23[0], rp.y, w0);
            ffma2(a01[1], rp.x, w1); ffma2(a23[1], rp.y, w1);
            ffma2(a01[2], rp.x, w2); ffma2(a23[2], rp.y, w2);
            ffma2(a01[3], rp.x, w3); ffma2(a23[3], rp.y, w3);
        }
    }

    const int o = tx * 4;
    float b0 = bias[o] + bias2[o],         b1 = bias[o + 1] + bias2[o + 1];
    float b2 = bias[o + 2] + bias2[o + 2], b3 = bias[o + 3] + bias2[o + 3];
    float res[4][4];
#pragma unroll
    for (int i = 0; i < 4; i++) {
        float2 p = unpack2(a01[i]);
        float2 q = unpack2(a23[i]);
        res[0][i] = p.x; res[1][i] = p.y; res[2][i] = q.x; res[3][i] = q.y;
    }
#pragma unroll
    for (int j = 0; j < 4; j++) {
        size_t row = (size_t)(nodeBase + ty * 4 + j + OFF_TR) * HID;
        uint2 hh;
        hh.x = f2h2(res[j][0] + b0, res[j][1] + b1);
        hh.y = f2h2(res[j][2] + b2, res[j][3] + b3);
        *(uint2*)(g_h0 + row + o) = hh;
    }
}

// -------- conv layer via fp16 mma.sync (m16n8k16, fp32 accum) --------
// 64 nodes/block, 128 threads; warp w: nodes w*16..+15, all 64 outputs.
__global__ void __launch_bounds__(128) conv_mma_kernel(
        int layer, const float* __restrict__ bias, float* __restrict__ outExt) {
    __shared__ __half A_s[64][136];
    __shared__ __half W_s[64][136];
    const __half* __restrict__ Hroot = layer ? g_h1 : g_h0;
    const __half* __restrict__ Wh = g_wh + layer * 64 * 128;

    const int tid  = threadIdx.x;
    const int lane = tid & 31;
    const int warp = tid >> 5;
    const int nodeBase = blockIdx.x * 64;

    for (int idx = tid; idx < 1024; idx += 128) {
        int n = idx >> 4, k8 = idx & 15;
        uint4 v;
        if (k8 < 8) v = *(const uint4*)(g_aggh + (size_t)(nodeBase + n) * HID + k8 * 8);
        else        v = *(const uint4*)(Hroot  + (size_t)(nodeBase + n) * HID + (k8 - 8) * 8);
        *(uint4*)&A_s[n][k8 * 8] = v;
    }
    for (int idx = tid; idx < 1024; idx += 128) {
        int o = idx >> 4, k8 = idx & 15;
        *(uint4*)&W_s[o][k8 * 8] = *(const uint4*)(Wh + o * 128 + k8 * 8);
    }
    __syncthreads();

    float c[8][4];
#pragma unroll
    for (int t8 = 0; t8 < 8; t8++)
#pragma unroll
        for (int i = 0; i < 4; i++) c[t8][i] = 0.f;

    const int row = warp * 16 + (lane >> 2);
    const int kq  = (lane & 3) * 2;
    const int nb  = lane >> 2;

#pragma unroll
    for (int s = 0; s < 8; s++) {
        int k0 = s * 16;
        unsigned a0 = *(const unsigned*)&A_s[row][k0 + kq];
        unsigned a1 = *(const unsigned*)&A_s[row + 8][k0 + kq];
        unsigned a2 = *(const unsigned*)&A_s[row][k0 + 8 + kq];
        unsigned a3 = *(const unsigned*)&A_s[row + 8][k0 + 8 + kq];
#pragma unroll
        for (int t8 = 0; t8 < 8; t8++) {
            unsigned b0 = *(const unsigned*)&W_s[t8 * 8 + nb][k0 + kq];
            unsigned b1 = *(const unsigned*)&W_s[t8 * 8 + nb][k0 + 8 + kq];
            mma_f16(c[t8], a0, a1, a2, a3, b0, b1);
        }
    }

    const int col0 = (lane & 3) * 2;
#pragma unroll
    for (int t8 = 0; t8 < 8; t8++) {
        int col = t8 * 8 + col0;
        float bc0 = bias[col], bc1 = bias[col + 1];
        float r0 = fmaxf(c[t8][0] + bc0, 0.f);
        float r1 = fmaxf(c[t8][1] + bc1, 0.f);
        float r2 = fmaxf(c[t8][2] + bc0, 0.f);
        float r3 = fmaxf(c[t8][3] + bc1, 0.f);
        size_t rA = (size_t)(nodeBase + row) * HID + col;
        size_t rB = (size_t)(nodeBase + row + 8) * HID + col;
        if (layer == 0) {
            *(unsigned*)(g_h1 + rA) = f2h2(r0, r1);
            *(unsigned*)(g_h1 + rB) = f2h2(r2, r3);
        } else {
            *(float2*)(outExt + rA) = make_float2(r0, r1);
            *(float2*)(outExt + rB) = make_float2(r2, r3);
        }
    }
}

extern "C" void kernel_launch(void* const* d_in, const int* in_sizes, int n_in,
                              void* d_out, int out_size) {
    const float* track_x   = (const float*)d_in[0];
    const int*   pl_tr_src = (const int*)d_in[1];
    const int*   pl_tr_dst = (const int*)d_in[2];
    const int*   tr_ar_src = (const int*)d_in[3];
    const int*   tr_ar_dst = (const int*)d_in[4];
    const float* pl_emb    = (const float*)d_in[5];
    const float* ar_emb    = (const float*)d_in[6];
    const float* track_W   = (const float*)d_in[7];
    const float* track_b   = (const float*)d_in[8];
    const float* type_emb  = (const float*)d_in[9];
    const float* conv_Wl   = (const float*)d_in[10];
    const float* conv_bl   = (const float*)d_in[11];
    const float* conv_Wr   = (const float*)d_in[12];
    float* out = (float*)d_out;

    const int E1 = in_sizes[1];
    const int E2 = in_sizes[3];
    const int ET = E1 + E2;

    // lazily created side stream + events for capture-fork overlap
    static cudaStream_t s2 = nullptr;
    static cudaEvent_t evFork = nullptr, evJoin = nullptr;
    if (s2 == nullptr) {
        cudaStreamCreateWithFlags(&s2, cudaStreamNonBlocking);
        cudaEventCreateWithFlags(&evFork, cudaEventDisableTiming);
        cudaEventCreateWithFlags(&evJoin, cudaEventDisableTiming);
    }
    bool fork = (s2 != nullptr && evFork != nullptr && evJoin != nullptr);
    cudaStream_t sCsr = fork ? s2 : (cudaStream_t)0;
    if (fork) {
        cudaEventRecord(evFork, 0);
        cudaStreamWaitEvent(s2, evFork, 0);
    }

    // ---- branch A (default stream): node features (fp16) ----
    {
        int total = (NUM_PL + NUM_AR) * (HID / 4);
        init_emb_kernel<<<(total + 255) / 256, 256>>>(pl_emb, ar_emb, type_emb);
    }
    track_gemm_kernel<<<NUM_TR / 32, 128>>>(track_x, track_W, track_b,
                                            type_emb + HID);

    // ---- branch B (side stream): weights + single-pass CSR ----
    wconv_kernel<<<(2 * 64 * 128 + 255) / 256, 256, 0, sCsr>>>(conv_Wl, conv_Wr);
    zero_deg_kernel<<<(NTOT + 255) / 256, 256, 0, sCsr>>>();
    fill_kernel<<<(ET + 255) / 256, 256, 0, sCsr>>>(pl_tr_src, pl_tr_dst, E1,
                                                    tr_ar_src, tr_ar_dst, E2);
    if (fork) {
        cudaEventRecord(evJoin, s2);
        cudaStreamWaitEvent((cudaStream_t)0, evJoin, 0);
    }

    // ---- layer 0: g_h0 -> g_h1 ----
    gather_kernel<<<(NTOT * 8 + 255) / 256, 256>>>(0);
    conv_mma_kernel<<<NTOT / 64, 128>>>(0, conv_bl, nullptr);

    // ---- layer 1: g_h1 -> d_out ----
    gather_kernel<<<(NTOT * 8 + 255) / 256, 256>>>(1);
    conv_mma_kernel<<<NTOT / 64, 128>>>(1, conv_bl + 64, out);
}

// round 12
// speedup vs baseline: 1.7662x; 1.0663x over previous
#include <cuda_runtime.h>
#include <cuda_fp16.h>

#define NUM_PL 50000
#define NUM_TR 100000
#define NUM_AR 10000
#define OFF_TR NUM_PL
#define OFF_AR (NUM_PL + NUM_TR)
#define NTOT   (NUM_PL + NUM_TR + NUM_AR)
#define HID    64
#define MAXDEG 128            // fixed adjacency stride; true max deg ~70
#define SPLIT  96000          // pipeline split (divisible by 64)

typedef unsigned long long ull;

// -------- scratch (device globals; no runtime allocation) --------
__device__ __align__(16) __half g_h0  [(size_t)NTOT * HID];
__device__ __align__(16) __half g_h1  [(size_t)NTOT * HID];
__device__ __align__(16) __half g_aggh[(size_t)NTOT * HID];
__device__ __align__(16) __half g_wh  [2 * 64 * 128];
__device__ int g_deg[NTOT];
__device__ __align__(16) int g_adj[(size_t)NTOT * MAXDEG];

// -------- helpers --------
__device__ __forceinline__ ull dup_f32(float x) {
    ull r; asm("mov.b64 %0, {%1,%1};" : "=l"(r) : "f"(x)); return r;
}
__device__ __forceinline__ void ffma2(ull& d, ull a, ull b) {
    asm("fma.rn.f32x2 %0, %1, %2, %3;" : "=l"(d) : "l"(a), "l"(b), "l"(d));
}
__device__ __forceinline__ float2 unpack2(ull v) {
    float2 f; asm("mov.b64 {%0,%1}, %2;" : "=f"(f.x), "=f"(f.y) : "l"(v)); return f;
}
__device__ __forceinline__ float2 h2f(unsigned u) {
    return __half22float2(*(const __half2*)&u);
}
__device__ __forceinline__ __half2 u2h(unsigned u) {
    return *(const __half2*)&u;
}
__device__ __forceinline__ unsigned f2h2(float a, float b) {
    __half2 h = __floats2half2_rn(a, b);
    return *(const unsigned*)&h;
}
__device__ __forceinline__ void mma_f16(float* c, unsigned a0, unsigned a1,
                                        unsigned a2, unsigned a3,
                                        unsigned b0, unsigned b1) {
    asm volatile("mma.sync.aligned.m16n8k16.row.col.f32.f16.f16.f32 "
                 "{%0,%1,%2,%3}, {%4,%5,%6,%7}, {%8,%9}, {%0,%1,%2,%3};"
                 : "+f"(c[0]), "+f"(c[1]), "+f"(c[2]), "+f"(c[3])
                 : "r"(a0), "r"(a1), "r"(a2), "r"(a3), "r"(b0), "r"(b1));
}

// -------- init playlist & artist rows (fp16) --------
__global__ void init_emb_kernel(const float* __restrict__ pl_emb,
                                const float* __restrict__ ar_emb,
                                const float* __restrict__ type_emb) {
    int t = blockIdx.x * blockDim.x + threadIdx.x;
    int total = (NUM_PL + NUM_AR) * (HID / 4);
    if (t >= total) return;
    int node = t >> 4;
    int c    = (t & 15) * 4;
    const float* src; const float* ty; size_t row;
    if (node < NUM_PL) {
        src = pl_emb + (size_t)node * HID;
        row = (size_t)node * HID;
        ty  = type_emb;
    } else {
        int a = node - NUM_PL;
        src = ar_emb + (size_t)a * HID;
        row = (size_t)(OFF_AR + a) * HID;
        ty  = type_emb + 2 * HID;
    }
    float4 v  = *(const float4*)(src + c);
    float4 tv = *(const float4*)(ty  + c);
    v.x += tv.x; v.y += tv.y; v.z += tv.z; v.w += tv.w;
    uint2 h; h.x = f2h2(v.x, v.y); h.y = f2h2(v.z, v.w);
    *(uint2*)(g_h0 + row + c) = h;
}

// -------- weight pre-convert: g_wh[l][o*128 + k] = fp16([Wl|Wr]) --------
__global__ void wconv_kernel(const float* __restrict__ Wl,
                             const float* __restrict__ Wr) {
    int t = blockIdx.x * blockDim.x + threadIdx.x;
    if (t >= 2 * 64 * 128) return;
    int l = t >> 13;
    int o = (t >> 7) & 63;
    int k = t & 127;
    float v = (k < 64) ? Wl[l * 64 * 64 + o * 64 + k]
                       : Wr[l * 64 * 64 + o * 64 + (k - 64)];
    g_wh[t] = __float2half_rn(v);
}

__global__ void zero_deg_kernel() {
    int i = blockIdx.x * blockDim.x + threadIdx.x;
    if (i < NTOT) g_deg[i] = 0;
}

// -------- single-pass CSR build --------
__global__ void fill_kernel(const int* __restrict__ s1, const int* __restrict__ d1, int n1,
                            const int* __restrict__ s2, const int* __restrict__ d2, int n2) {
    int e = blockIdx.x * blockDim.x + threadIdx.x;
    int a, b;
    if (e < n1)           { a = __ldg(s1 + e);               b = __ldg(d1 + e) + OFF_TR; }
    else if (e < n1 + n2) { a = __ldg(s2 + e - n1) + OFF_TR; b = __ldg(d2 + e - n1) + OFF_AR; }
    else return;
    int pa = atomicAdd(&g_deg[a], 1);
    if (pa < MAXDEG) g_adj[(size_t)a * MAXDEG + pa] = b;
    int pb = atomicAdd(&g_deg[b], 1);
    if (pb < MAXDEG) g_adj[(size_t)b * MAXDEG + pb] = a;
}

// -------- gather aggregation over node range [nodeStart, nodeStart+nodeCount) --------
__global__ void gather_kernel(int layer, int nodeStart, int nodeCount) {
    const __half* __restrict__ H = layer ? g_h1 : g_h0;
    int t = blockIdx.x * blockDim.x + threadIdx.x;
    int nrel = t >> 3;
    if (nrel >= nodeCount) return;
    int node = nodeStart + nrel;
    int c = (t & 7) * 8;
    const int* __restrict__ adj = g_adj + (size_t)node * MAXDEG;
    int d = g_deg[node];
    if (d > MAXDEG) d = MAXDEG;
    float acc[8];
#pragma unroll
    for (int j = 0; j < 8; j++) acc[j] = 0.f;

    int i = 0;
    for (; i + 4 <= d; i += 4) {
        int4 s = *(const int4*)(adj + i);
        uint4 v0 = *(const uint4*)(H + (size_t)s.x * HID + c);
        uint4 v1 = *(const uint4*)(H + (size_t)s.y * HID + c);
        uint4 v2 = *(const uint4*)(H + (size_t)s.z * HID + c);
        uint4 v3 = *(const uint4*)(H + (size_t)s.w * HID + c);
#pragma unroll
        for (int q = 0; q < 4; q++) {
            __half2 sh = __hadd2(__hadd2(u2h((&v0.x)[q]), u2h((&v1.x)[q])),
                                 __hadd2(u2h((&v2.x)[q]), u2h((&v3.x)[q])));
            float2 f = __half22float2(sh);
            acc[q * 2 + 0] += f.x; acc[q * 2 + 1] += f.y;
        }
    }
    for (; i < d; i++) {
        int s = __ldg(adj + i);
        uint4 v = *(const uint4*)(H + (size_t)s * HID + c);
#pragma unroll
        for (int q = 0; q < 4; q++) {
            float2 f = h2f((&v.x)[q]);
            acc[q * 2 + 0] += f.x; acc[q * 2 + 1] += f.y;
        }
    }

    float rd = 1.0f / (float)(d > 0 ? d : 1);
    uint4 hv;
    hv.x = f2h2(acc[0] * rd, acc[1] * rd);
    hv.y = f2h2(acc[2] * rd, acc[3] * rd);
    hv.z = f2h2(acc[4] * rd, acc[5] * rd);
    hv.w = f2h2(acc[6] * rd, acc[7] * rd);
    *(uint4*)(g_aggh + (size_t)node * HID + c) = hv;
}

// -------- track GEMM (exact f32x2): g_h0[tr] = fp16(track_x @ W^T + b + type_emb[1]) --------
__global__ void __launch_bounds__(128) track_gemm_kernel(
        const float* __restrict__ A, const float* __restrict__ W,
        const float* __restrict__ bias, const float* __restrict__ bias2) {
    __shared__ float Ws[64][68];
    __shared__ float rows[128][36];
    const int tid = threadIdx.x;
    const int tx  = tid & 15;
    const int ty  = tid >> 4;
    const int nodeBase = blockIdx.x * 32;

    for (int it = 0; it < 32; it++)
        rows[tid][it] = A[(size_t)(nodeBase + it) * 128 + tid];

    ull a01[4], a23[4];
#pragma unroll
    for (int i = 0; i < 4; i++) { a01[i] = 0ull; a23[i] = 0ull; }

    for (int h = 0; h < 2; h++) {
        __syncthreads();
        for (int idx = tid; idx < 64 * 64; idx += 128) {
            int o = idx >> 6, k = idx & 63;
            Ws[k][o] = W[(size_t)o * 128 + h * 64 + k];
        }
        __syncthreads();
#pragma unroll 8
        for (int k = 0; k < 64; k++) {
            ulonglong2 rp = *(const ulonglong2*)&rows[(h << 6) + k][ty * 4];
            float4 w = *(const float4*)&Ws[k][tx * 4];
            ull w0 = dup_f32(w.x), w1 = dup_f32(w.y);
            ull w2 = dup_f32(w.z), w3 = dup_f32(w.w);
            ffma2(a01[0], rp.x, w0); ffma2(a23[0], rp.y, w0);
            ffma2(a01[1], rp.x, w1); ffma2(a23[1], rp.y, w1);
            ffma2(a01[2], rp.x, w2); ffma2(a23[2], rp.y, w2);
            ffma2(a01[3], rp.x, w3); ffma2(a23[3], rp.y, w3);
        }
    }

    const int o = tx * 4;
    float b0 = bias[o] + bias2[o],         b1 = bias[o + 1] + bias2[o + 1];
    float b2 = bias[o + 2] + bias2[o + 2], b3 = bias[o + 3] + bias2[o + 3];
    float res[4][4];
#pragma unroll
    for (int i = 0; i < 4; i++) {
        float2 p = unpack2(a01[i]);
        float2 q = unpack2(a23[i]);
        res[0][i] = p.x; res[1][i] = p.y; res[2][i] = q.x; res[3][i] = q.y;
    }
#pragma unroll
    for (int j = 0; j < 4; j++) {
        size_t row = (size_t)(nodeBase + ty * 4 + j + OFF_TR) * HID;
        uint2 hh;
        hh.x = f2h2(res[j][0] + b0, res[j][1] + b1);
        hh.y = f2h2(res[j][2] + b2, res[j][3] + b3);
        *(uint2*)(g_h0 + row + o) = hh;
    }
}

// -------- conv layer via fp16 mma.sync over node range starting at nodeOffset --------
__global__ void __launch_bounds__(128) conv_mma_kernel(
        int layer, const float* __restrict__ bias, float* __restrict__ outExt,
        int nodeOffset) {
    __shared__ __half A_s[64][136];
    __shared__ __half W_s[64][136];
    const __half* __restrict__ Hroot = layer ? g_h1 : g_h0;
    const __half* __restrict__ Wh = g_wh + layer * 64 * 128;

    const int tid  = threadIdx.x;
    const int lane = tid & 31;
    const int warp = tid >> 5;
    const int nodeBase = nodeOffset + blockIdx.x * 64;

    for (int idx = tid; idx < 1024; idx += 128) {
        int n = idx >> 4, k8 = idx & 15;
        uint4 v;
        if (k8 < 8) v = *(const uint4*)(g_aggh + (size_t)(nodeBase + n) * HID + k8 * 8);
        else        v = *(const uint4*)(Hroot  + (size_t)(nodeBase + n) * HID + (k8 - 8) * 8);
        *(uint4*)&A_s[n][k8 * 8] = v;
    }
    for (int idx = tid; idx < 1024; idx += 128) {
        int o = idx >> 4, k8 = idx & 15;
        *(uint4*)&W_s[o][k8 * 8] = *(const uint4*)(Wh + o * 128 + k8 * 8);
    }
    __syncthreads();

    float c[8][4];
#pragma unroll
    for (int t8 = 0; t8 < 8; t8++)
#pragma unroll
        for (int i = 0; i < 4; i++) c[t8][i] = 0.f;

    const int row = warp * 16 + (lane >> 2);
    const int kq  = (lane & 3) * 2;
    const int nb  = lane >> 2;

#pragma unroll
    for (int s = 0; s < 8; s++) {
        int k0 = s * 16;
        unsigned a0 = *(const unsigned*)&A_s[row][k0 + kq];
        unsigned a1 = *(const unsigned*)&A_s[row + 8][k0 + kq];
        unsigned a2 = *(const unsigned*)&A_s[row][k0 + 8 + kq];
        unsigned a3 = *(const unsigned*)&A_s[row + 8][k0 + 8 + kq];
#pragma unroll
        for (int t8 = 0; t8 < 8; t8++) {
            unsigned b0 = *(const unsigned*)&W_s[t8 * 8 + nb][k0 + kq];
            unsigned b1 = *(const unsigned*)&W_s[t8 * 8 + nb][k0 + 8 + kq];
            mma_f16(c[t8], a0, a1, a2, a3, b0, b1);
        }
    }

    const int col0 = (lane & 3) * 2;
#pragma unroll
    for (int t8 = 0; t8 < 8; t8++) {
        int col = t8 * 8 + col0;
        float bc0 = bias[col], bc1 = bias[col + 1];
        float r0 = fmaxf(c[t8][0] + bc0, 0.f);
        float r1 = fmaxf(c[t8][1] + bc1, 0.f);
        float r2 = fmaxf(c[t8][2] + bc0, 0.f);
        float r3 = fmaxf(c[t8][3] + bc1, 0.f);
        size_t rA = (size_t)(nodeBase + row) * HID + col;
        size_t rB = (size_t)(nodeBase + row + 8) * HID + col;
        if (layer == 0) {
            *(unsigned*)(g_h1 + rA) = f2h2(r0, r1);
            *(unsigned*)(g_h1 + rB) = f2h2(r2, r3);
        } else {
            *(float2*)(outExt + rA) = make_float2(r0, r1);
            *(float2*)(outExt + rB) = make_float2(r2, r3);
        }
    }
}

extern "C" void kernel_launch(void* const* d_in, const int* in_sizes, int n_in,
                              void* d_out, int out_size) {
    const float* track_x   = (const float*)d_in[0];
    const int*   pl_tr_src = (const int*)d_in[1];
    const int*   pl_tr_dst = (const int*)d_in[2];
    const int*   tr_ar_src = (const int*)d_in[3];
    const int*   tr_ar_dst = (const int*)d_in[4];
    const float* pl_emb    = (const float*)d_in[5];
    const float* ar_emb    = (const float*)d_in[6];
    const float* track_W   = (const float*)d_in[7];
    const float* track_b   = (const float*)d_in[8];
    const float* type_emb  = (const float*)d_in[9];
    const float* conv_Wl   = (const float*)d_in[10];
    const float* conv_bl   = (const float*)d_in[11];
    const float* conv_Wr   = (const float*)d_in[12];
    float* out = (float*)d_out;

    const int E1 = in_sizes[1];
    const int E2 = in_sizes[3];
    const int ET = E1 + E2;
    const int H2N = NTOT - SPLIT;     // 64000

    // lazily created side stream + events
    static cudaStream_t s2 = nullptr;
    static cudaEvent_t evFork = nullptr, evB = nullptr;
    static cudaEvent_t e1 = nullptr, eC0 = nullptr, e4 = nullptr, eC1 = nullptr;
    if (s2 == nullptr) {
        cudaStreamCreateWithFlags(&s2, cudaStreamNonBlocking);
        cudaEventCreateWithFlags(&evFork, cudaEventDisableTiming);
        cudaEventCreateWithFlags(&evB, cudaEventDisableTiming);
        cudaEventCreateWithFlags(&e1, cudaEventDisableTiming);
        cudaEventCreateWithFlags(&eC0, cudaEventDisableTiming);
        cudaEventCreateWithFlags(&e4, cudaEventDisableTiming);
        cudaEventCreateWithFlags(&eC1, cudaEventDisableTiming);
    }

    cudaEventRecord(evFork, 0);
    cudaStreamWaitEvent(s2, evFork, 0);

    // ---- branch A (stream 0): features + weights ----
    {
        int total = (NUM_PL + NUM_AR) * (HID / 4);
        init_emb_kernel<<<(total + 255) / 256, 256>>>(pl_emb, ar_emb, type_emb);
    }
    track_gemm_kernel<<<NUM_TR / 32, 128>>>(track_x, track_W, track_b,
                                            type_emb + HID);
    wconv_kernel<<<(2 * 64 * 128 + 255) / 256, 256>>>(conv_Wl, conv_Wr);

    // ---- branch B (s2): CSR build ----
    zero_deg_kernel<<<(NTOT + 255) / 256, 256, 0, s2>>>();
    fill_kernel<<<(ET + 255) / 256, 256, 0, s2>>>(pl_tr_src, pl_tr_dst, E1,
                                                  tr_ar_src, tr_ar_dst, E2);
    cudaEventRecord(evB, s2);
    cudaStreamWaitEvent((cudaStream_t)0, evB, 0);

    // ==== layer 0 (split pipeline) ====
    gather_kernel<<<SPLIT * 8 / 256, 256>>>(0, 0, SPLIT);               // g0 H1
    cudaEventRecord(e1, 0);
    gather_kernel<<<H2N * 8 / 256, 256>>>(0, SPLIT, H2N);               // g0 H2
    conv_mma_kernel<<<H2N / 64, 128>>>(0, conv_bl, nullptr, SPLIT);     // c0 H2 (stream 0)
    cudaStreamWaitEvent(s2, e1, 0);
    conv_mma_kernel<<<SPLIT / 64, 128, 0, s2>>>(0, conv_bl, nullptr, 0);// c0 H1 (s2)
    cudaEventRecord(eC0, s2);
    cudaStreamWaitEvent((cudaStream_t)0, eC0, 0);

    // ==== layer 1 (split pipeline) ====
    gather_kernel<<<SPLIT * 8 / 256, 256>>>(1, 0, SPLIT);               // g1 H1
    cudaEventRecord(e4, 0);
    gather_kernel<<<H2N * 8 / 256, 256>>>(1, SPLIT, H2N);               // g1 H2
    cudaStreamWaitEvent(s2, e4, 0);
    conv_mma_kernel<<<SPLIT / 64, 128, 0, s2>>>(1, conv_bl + 64, out, 0);   // c1 H1 (s2)
    cudaEventRecord(eC1, s2);
    cudaStreamWaitEvent((cudaStream_t)0, eC1, 0);
    conv_mma_kernel<<<H2N / 64, 128>>>(1, conv_bl + 64, out, SPLIT);    // c1 H2 (stream 0, last)
}